// round 13
// baseline (speedup 1.0000x reference)
#include <cuda_runtime.h>
#include <cuda_fp16.h>
#include <math.h>
#include <stdint.h>

#define N_VERTS 100000
#define N_FACES 200000
#define DIM 512

// ===================== portable PTX helpers (sm_80+) =====================
__device__ __forceinline__ uint32_t smem_to_u32(const void* smem_ptr) {
    uint32_t addr;
    asm("{ .reg .u64 tmp; cvta.to.shared.u64 tmp, %1; cvt.u32.u64 %0, tmp; }"
        : "=r"(addr) : "l"(smem_ptr));
    return addr;
}

__device__ __forceinline__ void cp16(uint32_t dst, const void* src) {
    asm volatile("cp.async.cg.shared.global [%0], [%1], 16;"
                 :: "r"(dst), "l"(src) : "memory");
}

__device__ __forceinline__ void ldm_x4(uint32_t (&r)[4], uint32_t addr) {
    asm volatile("ldmatrix.sync.aligned.m8n8.x4.shared.b16 {%0,%1,%2,%3}, [%4];"
                 : "=r"(r[0]), "=r"(r[1]), "=r"(r[2]), "=r"(r[3]) : "r"(addr));
}

__device__ __forceinline__ void mma_f16(float (&d)[4], const uint32_t (&a)[4],
                                        uint32_t b0, uint32_t b1) {
    asm volatile(
        "mma.sync.aligned.m16n8k16.row.col.f32.f16.f16.f32 "
        "{%0,%1,%2,%3}, {%4,%5,%6,%7}, {%8,%9}, {%0,%1,%2,%3};"
        : "+f"(d[0]), "+f"(d[1]), "+f"(d[2]), "+f"(d[3])
        : "r"(a[0]), "r"(a[1]), "r"(a[2]), "r"(a[3]), "r"(b0), "r"(b1));
}

__device__ __forceinline__ uint32_t pack_h2(float a, float b) {
    __half2 t = __floats2half2_rn(a, b);
    return *(uint32_t*)&t;
}

// ===================== scratch (no allocations allowed) =====================
__device__ __half g_f_hi[(size_t)N_VERTS * DIM];   // split features
__device__ __half g_f_lo[(size_t)N_VERTS * DIM];
__device__ float  g_G[(size_t)N_VERTS * DIM];      // features @ W1
__device__ __half g_x_hi[(size_t)N_FACES * DIM];
__device__ __half g_x_lo[(size_t)N_FACES * DIM];
__device__ __half g_y_hi[(size_t)N_FACES * DIM];
__device__ __half g_y_lo[(size_t)N_FACES * DIM];
__device__ float  g_p12[2 * (size_t)N_FACES * 12]; // partial out12 per N-block
__device__ float  g_sum[N_VERTS * 3];
__device__ float  g_cnt[N_VERTS];
// transposed fp16 weights: Wt[n][k] = fp16(W[k][n])
__device__ __half g_w1t[DIM * DIM];
__device__ __half g_w2t[DIM * DIM];
__device__ __half g_w3t[256 * DIM];

// ====== prep: zero accumulators + convert all weights + split features =====
// range layout (in 128-lane float4 groups for the feature part):
#define PREP_W1   262144              // 512*512
#define PREP_W2   524288
#define PREP_W3   655360              // + 512*256
#define PREP_SUM  955360              // + 300000
#define PREP_CNT  1055360             // + 100000
#define PREP_FEAT (PREP_CNT + N_VERTS * 128)  // + 12,800,000 (f4 slots)

__global__ void prep_kernel(const float* __restrict__ W1,
                            const float* __restrict__ W2,
                            const float* __restrict__ W3,
                            const float* __restrict__ features) {
    int id = blockIdx.x * blockDim.x + threadIdx.x;
    if (id < PREP_W1) {
        int k = id / 512, n = id % 512;
        g_w1t[(size_t)n * DIM + k] = __float2half_rn(W1[id]);
    } else if (id < PREP_W2) {
        int i = id - PREP_W1;
        int k = i / 512, n = i % 512;
        g_w2t[(size_t)n * DIM + k] = __float2half_rn(W2[i]);
    } else if (id < PREP_W3) {
        int i = id - PREP_W2;
        int k = i / 256, n = i % 256;
        g_w3t[(size_t)n * DIM + k] = __float2half_rn(W3[i]);
    } else if (id < PREP_SUM) {
        g_sum[id - PREP_W3] = 0.0f;
    } else if (id < PREP_CNT) {
        g_cnt[id - PREP_SUM] = 0.0f;
    } else if (id < PREP_FEAT) {
        int i = id - PREP_CNT;          // 0 .. N_VERTS*128-1
        int r = i >> 7;                 // vertex row
        int c = i & 127;                // float4 column
        float4 x = ((const float4*)(features + (size_t)r * DIM))[c];
        float v[4] = {x.x, x.y, x.z, x.w};
        uint32_t ph[2], pl[2];
#pragma unroll
        for (int p = 0; p < 2; p++) {
            __half h0 = __float2half_rn(v[2 * p]);
            __half h1 = __float2half_rn(v[2 * p + 1]);
            ph[p] = (uint32_t)__half_as_ushort(h0) |
                    ((uint32_t)__half_as_ushort(h1) << 16);
            pl[p] = pack_h2(v[2 * p] - __half2float(h0),
                            v[2 * p + 1] - __half2float(h1));
        }
        *(uint2*)(g_f_hi + (size_t)r * DIM + c * 4) = make_uint2(ph[0], ph[1]);
        *(uint2*)(g_f_lo + (size_t)r * DIM + c * 4) = make_uint2(pl[0], pl[1]);
    }
}

// ===================== gather G rows + mean + bias + relu + split ==========
__global__ void gather_relu_split_kernel(const float* __restrict__ G,
                                         const int* __restrict__ faces,
                                         const float* __restrict__ b1,
                                         __half* __restrict__ outHi,
                                         __half* __restrict__ outLo) {
    int f = blockIdx.x;
    int c = threadIdx.x;  // 128 threads x float4
    int i0 = faces[f * 3 + 0];
    int i1 = faces[f * 3 + 1];
    int i2 = faces[f * 3 + 2];
    float4 a = ((const float4*)(G + (size_t)i0 * DIM))[c];
    float4 b = ((const float4*)(G + (size_t)i1 * DIM))[c];
    float4 d = ((const float4*)(G + (size_t)i2 * DIM))[c];
    float4 bb = __ldg((const float4*)&b1[c * 4]);
    const float k3 = 1.0f / 3.0f;
    float v[4];
    v[0] = fmaxf(fmaf(a.x + b.x + d.x, k3, bb.x), 0.0f);
    v[1] = fmaxf(fmaf(a.y + b.y + d.y, k3, bb.y), 0.0f);
    v[2] = fmaxf(fmaf(a.z + b.z + d.z, k3, bb.z), 0.0f);
    v[3] = fmaxf(fmaf(a.w + b.w + d.w, k3, bb.w), 0.0f);
    uint32_t ph[2], pl[2];
#pragma unroll
    for (int p = 0; p < 2; p++) {
        __half h0 = __float2half_rn(v[2 * p]);
        __half h1 = __float2half_rn(v[2 * p + 1]);
        ph[p] = (uint32_t)__half_as_ushort(h0) |
                ((uint32_t)__half_as_ushort(h1) << 16);
        pl[p] = pack_h2(v[2 * p] - __half2float(h0),
                        v[2 * p + 1] - __half2float(h1));
    }
    *(uint2*)(outHi + (size_t)f * DIM + c * 4) = make_uint2(ph[0], ph[1]);
    *(uint2*)(outLo + (size_t)f * DIM + c * 4) = make_uint2(pl[0], pl[1]);
}

// ===================== HMMA 2-pass fp16 GEMM (2-stage, 2 CTAs/SM) ==========
// out = act(A_full @ fp16(Wt)^T + bias); A given exactly as fp16 hi+lo.
// OUT_MODE 0: relu+bias -> fp16 hi/lo.
// OUT_MODE 2: raw -> f32.
// OUT_MODE 3: relu+bias, then fused head: p12 = relu_tile @ W4_slice (per N-block).
#define ROW_B       80              // 64B data + 16B pad per smem row
#define BUF_BYTES   (128 * ROW_B)   // 10240
#define STG_BYTES   (3 * BUF_BYTES) // 30720 (Ahi, Alo, B)
#define SOUT_BYTES  67584           // 128*132*4
#define SM_BIAS_OFF SOUT_BYTES
#define SM_W4_OFF   (SOUT_BYTES + 512)
#define SM_TOTAL_G  SOUT_BYTES               // modes 0/2
#define SM_TOTAL_G3 (SOUT_BYTES + 512 + 6144) // mode 3: + sbias + W4 slice

template <int N_TOTAL, int OUT_MODE>
__global__ void __launch_bounds__(256, 2)
gemm_hmma(const __half* __restrict__ Ahi,
          const __half* __restrict__ Alo,
          const __half* __restrict__ Bw,
          const float* __restrict__ bias,
          void* __restrict__ outHiV, void* __restrict__ outLoV,
          int M,
          const float* __restrict__ W4p, float* __restrict__ p12) {
    extern __shared__ char smem[];
    const uint32_t su = smem_to_u32(smem);
    const int tid = threadIdx.x;
    const int m0 = blockIdx.y * 128;
    const int n0 = blockIdx.x * 128;

    if (OUT_MODE == 3) {
        float* sbias = (float*)(smem + SM_BIAS_OFF);
        float* w4s = (float*)(smem + SM_W4_OFF);
        if (tid < 128) sbias[tid] = bias[n0 + tid];
        for (int i = tid; i < 128 * 12; i += 256)
            w4s[i] = W4p[(size_t)(n0 + i / 12) * 12 + (i % 12)];
    }

    const int lane = tid & 31;
    const int warp = tid >> 5;
    const int wm = warp & 3;   // 4 warps along M
    const int wn = warp >> 2;  // 2 warps along N

    const uint32_t aRow = wm * 32 + (lane & 15);
    const uint32_t aCol = (lane >> 4) * 16;
    const uint32_t bRow = wn * 64 + (lane & 7) + ((lane & 16) >> 1);
    const uint32_t bCol = (lane & 8) ? 16u : 0u;

    const uint32_t aHiB = su + aRow * ROW_B + aCol;                  // buf0
    const uint32_t aLoB = aHiB + BUF_BYTES;                          // buf1
    const uint32_t bB   = su + 2 * BUF_BYTES + bRow * ROW_B + bCol;  // buf2

    const int ldRowHalf = tid >> 2;
    const int ldQ = tid & 3;

    float acc[2][8][4];
#pragma unroll
    for (int t = 0; t < 2; t++)
#pragma unroll
        for (int j = 0; j < 8; j++)
#pragma unroll
            for (int e = 0; e < 4; e++) acc[t][j][e] = 0.0f;

    auto load_stage = [&](int stage, int kc) {
        const int k0 = kc * 32;
        const uint32_t stageBase = (uint32_t)stage * STG_BYTES;
#pragma unroll
        for (int i = 0; i < 6; i++) {
            const int buf = i >> 1;
            const int r = (i & 1) * 64 + ldRowHalf;
            const uint32_t dst = su + stageBase + buf * BUF_BYTES +
                                 r * ROW_B + ldQ * 16;
            const __half* srcp;
            if (buf == 0) {
                int gr = m0 + r; if (gr >= M) gr = M - 1;
                srcp = Ahi + (size_t)gr * DIM + k0 + ldQ * 8;
            } else if (buf == 1) {
                int gr = m0 + r; if (gr >= M) gr = M - 1;
                srcp = Alo + (size_t)gr * DIM + k0 + ldQ * 8;
            } else {
                srcp = Bw + (size_t)(n0 + r) * DIM + k0 + ldQ * 8;
            }
            cp16(dst, srcp);
        }
        asm volatile("cp.async.commit_group;" ::: "memory");
    };

    load_stage(0, 0);
    load_stage(1, 1);

    for (int kc = 0; kc < 16; kc++) {
        if (kc == 15) {
            asm volatile("cp.async.wait_group 0;" ::: "memory");
        } else {
            asm volatile("cp.async.wait_group 1;" ::: "memory");
        }
        __syncthreads();

        const uint32_t sb = (uint32_t)(kc & 1) * STG_BYTES;
#pragma unroll
        for (int h = 0; h < 2; h++) {
            const uint32_t hoff = sb + h * 32;
            uint32_t ah[2][4], al[2][4];
            ldm_x4(ah[0], aHiB + hoff);
            ldm_x4(ah[1], aHiB + hoff + 16 * ROW_B);
            ldm_x4(al[0], aLoB + hoff);
            ldm_x4(al[1], aLoB + hoff + 16 * ROW_B);
#pragma unroll
            for (int p = 0; p < 4; p++) {
                uint32_t bw[4];
                ldm_x4(bw, bB + hoff + p * (16 * ROW_B));
#pragma unroll
                for (int t = 0; t < 2; t++) {
                    mma_f16(acc[t][2 * p],     ah[t], bw[0], bw[1]);
                    mma_f16(acc[t][2 * p + 1], ah[t], bw[2], bw[3]);
                    mma_f16(acc[t][2 * p],     al[t], bw[0], bw[1]);
                    mma_f16(acc[t][2 * p + 1], al[t], bw[2], bw[3]);
                }
            }
        }
        __syncthreads();
        if (kc + 2 < 16) load_stage(kc & 1, kc + 2);
    }

    // -------- epilogue --------
    float* sout = (float*)smem;
    if (OUT_MODE == 3) {
        const float* sbias = (const float*)(smem + SM_BIAS_OFF);
#pragma unroll
        for (int t = 0; t < 2; t++)
#pragma unroll
            for (int j = 0; j < 8; j++) {
                const int row = wm * 32 + t * 16 + (lane >> 2);
                const int col = wn * 64 + j * 8 + (lane & 3) * 2;
                sout[row * 132 + col] =
                    fmaxf(acc[t][j][0] + sbias[col], 0.0f);
                sout[row * 132 + col + 1] =
                    fmaxf(acc[t][j][1] + sbias[col + 1], 0.0f);
                sout[(row + 8) * 132 + col] =
                    fmaxf(acc[t][j][2] + sbias[col], 0.0f);
                sout[(row + 8) * 132 + col + 1] =
                    fmaxf(acc[t][j][3] + sbias[col + 1], 0.0f);
            }
        __syncthreads();
        const float* w4s = (const float*)(smem + SM_W4_OFF);
        const int row = tid >> 1;
        const int jh = (tid & 1) * 6;
        float p[6] = {0, 0, 0, 0, 0, 0};
        for (int c = 0; c < 128; c++) {
            const float h = sout[row * 132 + c];
#pragma unroll
            for (int jj = 0; jj < 6; jj++)
                p[jj] = fmaf(h, w4s[c * 12 + jh + jj], p[jj]);
        }
        const int gr = m0 + row;
        if (gr < M) {
            float* dst = p12 + ((size_t)blockIdx.x * M + gr) * 12 + jh;
#pragma unroll
            for (int jj = 0; jj < 6; jj++) dst[jj] = p[jj];
        }
        return;
    }

#pragma unroll
    for (int t = 0; t < 2; t++)
#pragma unroll
        for (int j = 0; j < 8; j++) {
            const int row = wm * 32 + t * 16 + (lane >> 2);
            const int col = wn * 64 + j * 8 + (lane & 3) * 2;
            sout[row * 132 + col]           = acc[t][j][0];
            sout[row * 132 + col + 1]       = acc[t][j][1];
            sout[(row + 8) * 132 + col]     = acc[t][j][2];
            sout[(row + 8) * 132 + col + 1] = acc[t][j][3];
        }
    __syncthreads();

#pragma unroll
    for (int i = 0; i < 16; i++) {
        const int lin = tid + i * 256;
        const int row = lin >> 5;
        const int q = lin & 31;
        const int gr = m0 + row;
        if (gr >= M) continue;
        float4 v = *(float4*)&sout[row * 132 + q * 4];
        if (OUT_MODE == 0) {
            const float4 bb = __ldg((const float4*)&bias[n0 + q * 4]);
            v.x = fmaxf(v.x + bb.x, 0.0f);
            v.y = fmaxf(v.y + bb.y, 0.0f);
            v.z = fmaxf(v.z + bb.z, 0.0f);
            v.w = fmaxf(v.w + bb.w, 0.0f);
            __half h0 = __float2half_rn(v.x);
            __half h1 = __float2half_rn(v.y);
            __half h2 = __float2half_rn(v.z);
            __half h3 = __float2half_rn(v.w);
            uint2 vh, vl;
            vh.x = (uint32_t)__half_as_ushort(h0) |
                   ((uint32_t)__half_as_ushort(h1) << 16);
            vh.y = (uint32_t)__half_as_ushort(h2) |
                   ((uint32_t)__half_as_ushort(h3) << 16);
            vl.x = pack_h2(v.x - __half2float(h0), v.y - __half2float(h1));
            vl.y = pack_h2(v.z - __half2float(h2), v.w - __half2float(h3));
            const size_t off = (size_t)gr * N_TOTAL + n0 + q * 4;
            *(uint2*)((__half*)outHiV + off) = vh;
            *(uint2*)((__half*)outLoV + off) = vl;
        } else {
            *(float4*)((float*)outHiV + (size_t)gr * N_TOTAL + n0 + q * 4) = v;
        }
    }
}

// ============== analytic 3x3 symmetric eigenvector helpers ==============
__device__ __forceinline__ void cross3(const double a[3], const double b[3],
                                       double c[3]) {
    c[0] = a[1] * b[2] - a[2] * b[1];
    c[1] = a[2] * b[0] - a[0] * b[2];
    c[2] = a[0] * b[1] - a[1] * b[0];
}

__device__ double eigvec3(const double C[6], double lam, double v[3]) {
    double r0[3] = {C[0] - lam, C[3], C[4]};
    double r1[3] = {C[3], C[1] - lam, C[5]};
    double r2[3] = {C[4], C[5], C[2] - lam};
    double c0[3], c1[3], c2[3];
    cross3(r0, r1, c0);
    cross3(r0, r2, c1);
    cross3(r1, r2, c2);
    double n0 = c0[0] * c0[0] + c0[1] * c0[1] + c0[2] * c0[2];
    double n1 = c1[0] * c1[0] + c1[1] * c1[1] + c1[2] * c1[2];
    double n2 = c2[0] * c2[0] + c2[1] * c2[1] + c2[2] * c2[2];
    const double* best = c0;
    double nb = n0;
    if (n1 > nb) { best = c1; nb = n1; }
    if (n2 > nb) { best = c2; nb = n2; }
    if (nb > 0.0) {
        double inv = 1.0 / sqrt(nb);
        v[0] = best[0] * inv; v[1] = best[1] * inv; v[2] = best[2] * inv;
    }
    return nb;
}

__device__ __forceinline__ void arb_perp(const double w[3], double v[3]) {
    if (fabs(w[0]) > 0.5) {
        double inv = 1.0 / sqrt(w[0] * w[0] + w[1] * w[1]);
        v[0] = w[1] * inv; v[1] = -w[0] * inv; v[2] = 0.0;
    } else {
        double inv = 1.0 / sqrt(w[1] * w[1] + w[2] * w[2]);
        v[0] = 0.0; v[1] = w[2] * inv; v[2] = -w[1] * inv;
    }
}

// ===================== procrustes (analytic) + transform + scatter ==========
__global__ void procrustes_kernel(const float* __restrict__ p12,
                                  const float* __restrict__ b4,
                                  const float* __restrict__ verts,
                                  const int* __restrict__ faces,
                                  float* __restrict__ out_trans,
                                  float* __restrict__ out_rot) {
    int f = blockIdx.x * blockDim.x + threadIdx.x;
    if (f >= N_FACES) return;

    const size_t HALF = (size_t)N_FACES * 12;
    float o12[12];
#pragma unroll
    for (int j = 0; j < 12; j++)
        o12[j] = p12[(size_t)f * 12 + j] + p12[HALF + (size_t)f * 12 + j] +
                 __ldg(&b4[j]);

    double Mm[3][3];
#pragma unroll
    for (int i = 0; i < 3; i++)
#pragma unroll
        for (int j = 0; j < 3; j++)
            Mm[i][j] = (double)o12[i * 3 + j];

    double C[6];
    C[0] = Mm[0][0] * Mm[0][0] + Mm[1][0] * Mm[1][0] + Mm[2][0] * Mm[2][0];
    C[1] = Mm[0][1] * Mm[0][1] + Mm[1][1] * Mm[1][1] + Mm[2][1] * Mm[2][1];
    C[2] = Mm[0][2] * Mm[0][2] + Mm[1][2] * Mm[1][2] + Mm[2][2] * Mm[2][2];
    C[3] = Mm[0][0] * Mm[0][1] + Mm[1][0] * Mm[1][1] + Mm[2][0] * Mm[2][1];
    C[4] = Mm[0][0] * Mm[0][2] + Mm[1][0] * Mm[1][2] + Mm[2][0] * Mm[2][2];
    C[5] = Mm[0][1] * Mm[0][2] + Mm[1][1] * Mm[1][2] + Mm[2][1] * Mm[2][2];

    double v1[3], v2[3], v3[3];
    double mtr = (C[0] + C[1] + C[2]) * (1.0 / 3.0);
    double K0 = C[0] - mtr, K1 = C[1] - mtr, K2 = C[2] - mtr;
    double p2 = K0 * K0 + K1 * K1 + K2 * K2 +
                2.0 * (C[3] * C[3] + C[4] * C[4] + C[5] * C[5]);
    double p = p2 * (1.0 / 6.0);
    double sp = sqrt(p);

    bool ident = (sp < 1e-100 + 1e-14 * fabs(mtr));
    if (ident) {
        v1[0] = 1; v1[1] = 0; v1[2] = 0;
        v2[0] = 0; v2[1] = 1; v2[2] = 0;
        v3[0] = 0; v3[1] = 0; v3[2] = 1;
    } else {
        double detK = K0 * (K1 * K2 - C[5] * C[5])
                    - C[3] * (C[3] * K2 - C[5] * C[4])
                    + C[4] * (C[3] * C[5] - K1 * C[4]);
        double r = detK / (2.0 * sp * sp * sp);
        r = fmin(1.0, fmax(-1.0, r));
        float phi = acosf((float)r) * (1.0f / 3.0f);
        double lam1 = mtr + 2.0 * sp * (double)cosf(phi);
        double lam3 = mtr + 2.0 * sp * (double)cosf(phi + 2.0943951023931953f);

        const double thr = 1e-24 * p2 * p2;
        double n1 = eigvec3(C, lam1, v1);
        double n3 = eigvec3(C, lam3, v3);
        if (n1 > thr && n3 > thr) {
            cross3(v3, v1, v2);
            double inv = 1.0 / sqrt(v2[0] * v2[0] + v2[1] * v2[1] + v2[2] * v2[2]);
            v2[0] *= inv; v2[1] *= inv; v2[2] *= inv;
        } else if (n3 > thr) {
            arb_perp(v3, v1);
            cross3(v3, v1, v2);
        } else if (n1 > thr) {
            arb_perp(v1, v3);
            cross3(v3, v1, v2);
        } else {
            v1[0] = 1; v1[1] = 0; v1[2] = 0;
            v2[0] = 0; v2[1] = 1; v2[2] = 0;
            v3[0] = 0; v3[1] = 0; v3[2] = 1;
        }
    }

    double b1c[3], b2c[3];
#pragma unroll
    for (int i = 0; i < 3; i++) {
        b1c[i] = Mm[i][0] * v1[0] + Mm[i][1] * v1[1] + Mm[i][2] * v1[2];
        b2c[i] = Mm[i][0] * v2[0] + Mm[i][1] * v2[1] + Mm[i][2] * v2[2];
    }

    double u1[3], u2[3], u3[3];
    double nb1 = sqrt(b1c[0] * b1c[0] + b1c[1] * b1c[1] + b1c[2] * b1c[2]);
    double in1 = 1.0 / fmax(nb1, 1e-150);
#pragma unroll
    for (int i = 0; i < 3; i++) u1[i] = b1c[i] * in1;
    double d12 = u1[0] * b2c[0] + u1[1] * b2c[1] + u1[2] * b2c[2];
    double w[3];
#pragma unroll
    for (int i = 0; i < 3; i++) w[i] = b2c[i] - d12 * u1[i];
    double nb2 = sqrt(w[0] * w[0] + w[1] * w[1] + w[2] * w[2]);
    double in2 = 1.0 / fmax(nb2, 1e-150);
#pragma unroll
    for (int i = 0; i < 3; i++) u2[i] = w[i] * in2;
    u3[0] = u1[1] * u2[2] - u1[2] * u2[1];
    u3[1] = u1[2] * u2[0] - u1[0] * u2[2];
    u3[2] = u1[0] * u2[1] - u1[1] * u2[0];

    float R[3][3];
#pragma unroll
    for (int i = 0; i < 3; i++) {
        R[i][0] = (float)(u1[i] * v1[0] + u2[i] * v2[0] + u3[i] * v3[0]);
        R[i][1] = (float)(u1[i] * v1[1] + u2[i] * v2[1] + u3[i] * v3[1]);
        R[i][2] = (float)(u1[i] * v1[2] + u2[i] * v2[2] + u3[i] * v3[2]);
    }

#pragma unroll
    for (int i = 0; i < 3; i++)
#pragma unroll
        for (int j = 0; j < 3; j++)
            out_rot[(size_t)f * 9 + i * 3 + j] = R[i][j];

    float t0 = o12[9];
    float t1 = o12[10];
    float t2 = o12[11];

#pragma unroll
    for (int c = 0; c < 3; c++) {
        int vi = faces[f * 3 + c];
        float vx = verts[(size_t)vi * 3 + 0];
        float vy = verts[(size_t)vi * 3 + 1];
        float vz = verts[(size_t)vi * 3 + 2];
        float tvx = vx * R[0][0] + vy * R[1][0] + vz * R[2][0] + t0;
        float tvy = vx * R[0][1] + vy * R[1][1] + vz * R[2][1] + t1;
        float tvz = vx * R[0][2] + vy * R[1][2] + vz * R[2][2] + t2;
        out_trans[(size_t)f * 9 + c * 3 + 0] = tvx;
        out_trans[(size_t)f * 9 + c * 3 + 1] = tvy;
        out_trans[(size_t)f * 9 + c * 3 + 2] = tvz;
        atomicAdd(&g_sum[vi * 3 + 0], tvx);
        atomicAdd(&g_sum[vi * 3 + 1], tvy);
        atomicAdd(&g_sum[vi * 3 + 2], tvz);
        atomicAdd(&g_cnt[vi], 1.0f);
    }
}

// ===================== finalize segment mean =====================
__global__ void finalize_kernel(float* __restrict__ out_vfeat) {
    int v = blockIdx.x * blockDim.x + threadIdx.x;
    if (v >= N_VERTS) return;
    float c = fmaxf(g_cnt[v], 1.0f);
    float inv = 1.0f / c;
    out_vfeat[v * 3 + 0] = g_sum[v * 3 + 0] * inv;
    out_vfeat[v * 3 + 1] = g_sum[v * 3 + 1] * inv;
    out_vfeat[v * 3 + 2] = g_sum[v * 3 + 2] * inv;
}

// ===================== launch =====================
extern "C" void kernel_launch(void* const* d_in, const int* in_sizes, int n_in,
                              void* d_out, int out_size) {
    const float* verts    = (const float*)d_in[0];
    const float* features = (const float*)d_in[1];
    const int*   faces    = (const int*)d_in[2];
    const float* W1 = (const float*)d_in[3];
    const float* b1 = (const float*)d_in[4];
    const float* W2 = (const float*)d_in[5];
    const float* b2 = (const float*)d_in[6];
    const float* W3 = (const float*)d_in[7];
    const float* b3 = (const float*)d_in[8];
    const float* W4 = (const float*)d_in[9];
    const float* b4 = (const float*)d_in[10];

    float* out = (float*)d_out;
    float* out_vfeat = out;
    float* out_trans = out + (size_t)N_VERTS * 3;
    float* out_rot   = out_trans + (size_t)N_FACES * 9;

    __half *p_f_hi, *p_f_lo, *p_x_hi, *p_x_lo, *p_y_hi, *p_y_lo;
    __half *p_w1t, *p_w2t, *p_w3t;
    float *p_G, *p_p12;
    cudaGetSymbolAddress((void**)&p_f_hi, g_f_hi);
    cudaGetSymbolAddress((void**)&p_f_lo, g_f_lo);
    cudaGetSymbolAddress((void**)&p_G, g_G);
    cudaGetSymbolAddress((void**)&p_x_hi, g_x_hi);
    cudaGetSymbolAddress((void**)&p_x_lo, g_x_lo);
    cudaGetSymbolAddress((void**)&p_y_hi, g_y_hi);
    cudaGetSymbolAddress((void**)&p_y_lo, g_y_lo);
    cudaGetSymbolAddress((void**)&p_w1t, g_w1t);
    cudaGetSymbolAddress((void**)&p_w2t, g_w2t);
    cudaGetSymbolAddress((void**)&p_w3t, g_w3t);
    cudaGetSymbolAddress((void**)&p_p12, g_p12);

    cudaFuncSetAttribute(gemm_hmma<512, 0>,
                         cudaFuncAttributeMaxDynamicSharedMemorySize, SM_TOTAL_G);
    cudaFuncSetAttribute(gemm_hmma<512, 2>,
                         cudaFuncAttributeMaxDynamicSharedMemorySize, SM_TOTAL_G);
    cudaFuncSetAttribute(gemm_hmma<256, 3>,
                         cudaFuncAttributeMaxDynamicSharedMemorySize, SM_TOTAL_G3);

    // 1. prep: zero accumulators + convert weights + split features (1 launch)
    prep_kernel<<<(PREP_FEAT + 255) / 256, 256>>>(W1, W2, W3, features);

    // 2. G = features @ W1  (M = N_VERTS, raw f32 out)
    {
        dim3 blk(256);
        dim3 gG(4, (N_VERTS + 127) / 128);
        gemm_hmma<512, 2><<<gG, blk, SM_TOTAL_G>>>(p_f_hi, p_f_lo, p_w1t,
                                                   nullptr, p_G, nullptr, N_VERTS,
                                                   nullptr, nullptr);
    }

    // 3. h1 = relu(mean(G rows) + b1) -> fp16 split (per-face)
    gather_relu_split_kernel<<<N_FACES, 128>>>(p_G, faces, b1, p_x_hi, p_x_lo);

    // 4. layer 2; layer 3 fused with W4 head -> partial out12
    {
        dim3 blk(256);
        dim3 g12(4, (N_FACES + 127) / 128);
        gemm_hmma<512, 0><<<g12, blk, SM_TOTAL_G>>>(p_x_hi, p_x_lo, p_w2t,
                                                    b2, p_y_hi, p_y_lo, N_FACES,
                                                    nullptr, nullptr);
        dim3 g3(2, (N_FACES + 127) / 128);
        gemm_hmma<256, 3><<<g3, blk, SM_TOTAL_G3>>>(p_y_hi, p_y_lo, p_w3t,
                                                    b3, nullptr, nullptr, N_FACES,
                                                    W4, p_p12);
    }

    // 5. procrustes (analytic eigensolver) + transform + scatter
    procrustes_kernel<<<(N_FACES + 255) / 256, 256>>>(p_p12, b4, verts, faces,
                                                      out_trans, out_rot);

    // 6. segment mean
    finalize_kernel<<<(N_VERTS + 255) / 256, 256>>>(out_vfeat);
}

// round 14
// speedup vs baseline: 1.0069x; 1.0069x over previous
#include <cuda_runtime.h>
#include <cuda_fp16.h>
#include <math.h>
#include <stdint.h>

#define N_VERTS 100000
#define N_FACES 200000
#define DIM 512

// ===================== portable PTX helpers (sm_80+) =====================
__device__ __forceinline__ uint32_t smem_to_u32(const void* smem_ptr) {
    uint32_t addr;
    asm("{ .reg .u64 tmp; cvta.to.shared.u64 tmp, %1; cvt.u32.u64 %0, tmp; }"
        : "=r"(addr) : "l"(smem_ptr));
    return addr;
}

__device__ __forceinline__ void cp16(uint32_t dst, const void* src) {
    asm volatile("cp.async.cg.shared.global [%0], [%1], 16;"
                 :: "r"(dst), "l"(src) : "memory");
}

__device__ __forceinline__ void ldm_x4(uint32_t (&r)[4], uint32_t addr) {
    asm volatile("ldmatrix.sync.aligned.m8n8.x4.shared.b16 {%0,%1,%2,%3}, [%4];"
                 : "=r"(r[0]), "=r"(r[1]), "=r"(r[2]), "=r"(r[3]) : "r"(addr));
}

__device__ __forceinline__ void mma_f16(float (&d)[4], const uint32_t (&a)[4],
                                        uint32_t b0, uint32_t b1) {
    asm volatile(
        "mma.sync.aligned.m16n8k16.row.col.f32.f16.f16.f32 "
        "{%0,%1,%2,%3}, {%4,%5,%6,%7}, {%8,%9}, {%0,%1,%2,%3};"
        : "+f"(d[0]), "+f"(d[1]), "+f"(d[2]), "+f"(d[3])
        : "r"(a[0]), "r"(a[1]), "r"(a[2]), "r"(a[3]), "r"(b0), "r"(b1));
}

__device__ __forceinline__ uint32_t pack_h2(float a, float b) {
    __half2 t = __floats2half2_rn(a, b);
    return *(uint32_t*)&t;
}

// ===================== scratch (no allocations allowed) =====================
__device__ __half g_f_hi[(size_t)N_VERTS * DIM];   // split features
__device__ __half g_f_lo[(size_t)N_VERTS * DIM];
__device__ float  g_G[(size_t)N_VERTS * DIM];      // features @ W1
__device__ __half g_x_hi[(size_t)N_FACES * DIM];
__device__ __half g_x_lo[(size_t)N_FACES * DIM];
__device__ __half g_y_hi[(size_t)N_FACES * DIM];
__device__ __half g_y_lo[(size_t)N_FACES * DIM];
__device__ float  g_p12[2 * (size_t)N_FACES * 12]; // partial out12 per N-block
__device__ float  g_sum[N_VERTS * 3];
__device__ float  g_cnt[N_VERTS];
// transposed fp16 weights: Wt[n][k] = fp16(W[k][n])
__device__ __half g_w1t[DIM * DIM];
__device__ __half g_w2t[DIM * DIM];
__device__ __half g_w3t[256 * DIM];

// ====== prep: zero accumulators + convert all weights + split features =====
#define PREP_W1   262144              // 512*512
#define PREP_W2   524288
#define PREP_W3   655360              // + 512*256
#define PREP_SUM  955360              // + 300000
#define PREP_CNT  1055360             // + 100000
#define PREP_FEAT (PREP_CNT + N_VERTS * 128)  // + 12,800,000 (f4 slots)

__global__ void prep_kernel(const float* __restrict__ W1,
                            const float* __restrict__ W2,
                            const float* __restrict__ W3,
                            const float* __restrict__ features) {
    int id = blockIdx.x * blockDim.x + threadIdx.x;
    if (id < PREP_W1) {
        int k = id / 512, n = id % 512;
        g_w1t[(size_t)n * DIM + k] = __float2half_rn(W1[id]);
    } else if (id < PREP_W2) {
        int i = id - PREP_W1;
        int k = i / 512, n = i % 512;
        g_w2t[(size_t)n * DIM + k] = __float2half_rn(W2[i]);
    } else if (id < PREP_W3) {
        int i = id - PREP_W2;
        int k = i / 256, n = i % 256;
        g_w3t[(size_t)n * DIM + k] = __float2half_rn(W3[i]);
    } else if (id < PREP_SUM) {
        g_sum[id - PREP_W3] = 0.0f;
    } else if (id < PREP_CNT) {
        g_cnt[id - PREP_SUM] = 0.0f;
    } else if (id < PREP_FEAT) {
        int i = id - PREP_CNT;          // 0 .. N_VERTS*128-1
        int r = i >> 7;                 // vertex row
        int c = i & 127;                // float4 column
        float4 x = ((const float4*)(features + (size_t)r * DIM))[c];
        float v[4] = {x.x, x.y, x.z, x.w};
        uint32_t ph[2], pl[2];
#pragma unroll
        for (int p = 0; p < 2; p++) {
            __half h0 = __float2half_rn(v[2 * p]);
            __half h1 = __float2half_rn(v[2 * p + 1]);
            ph[p] = (uint32_t)__half_as_ushort(h0) |
                    ((uint32_t)__half_as_ushort(h1) << 16);
            pl[p] = pack_h2(v[2 * p] - __half2float(h0),
                            v[2 * p + 1] - __half2float(h1));
        }
        *(uint2*)(g_f_hi + (size_t)r * DIM + c * 4) = make_uint2(ph[0], ph[1]);
        *(uint2*)(g_f_lo + (size_t)r * DIM + c * 4) = make_uint2(pl[0], pl[1]);
    }
}

// ===================== gather G rows + mean + bias + relu + split ==========
__global__ void gather_relu_split_kernel(const float* __restrict__ G,
                                         const int* __restrict__ faces,
                                         const float* __restrict__ b1,
                                         __half* __restrict__ outHi,
                                         __half* __restrict__ outLo) {
    int f = blockIdx.x;
    int c = threadIdx.x;  // 128 threads x float4
    int i0 = faces[f * 3 + 0];
    int i1 = faces[f * 3 + 1];
    int i2 = faces[f * 3 + 2];
    float4 a = ((const float4*)(G + (size_t)i0 * DIM))[c];
    float4 b = ((const float4*)(G + (size_t)i1 * DIM))[c];
    float4 d = ((const float4*)(G + (size_t)i2 * DIM))[c];
    float4 bb = __ldg((const float4*)&b1[c * 4]);
    const float k3 = 1.0f / 3.0f;
    float v[4];
    v[0] = fmaxf(fmaf(a.x + b.x + d.x, k3, bb.x), 0.0f);
    v[1] = fmaxf(fmaf(a.y + b.y + d.y, k3, bb.y), 0.0f);
    v[2] = fmaxf(fmaf(a.z + b.z + d.z, k3, bb.z), 0.0f);
    v[3] = fmaxf(fmaf(a.w + b.w + d.w, k3, bb.w), 0.0f);
    uint32_t ph[2], pl[2];
#pragma unroll
    for (int p = 0; p < 2; p++) {
        __half h0 = __float2half_rn(v[2 * p]);
        __half h1 = __float2half_rn(v[2 * p + 1]);
        ph[p] = (uint32_t)__half_as_ushort(h0) |
                ((uint32_t)__half_as_ushort(h1) << 16);
        pl[p] = pack_h2(v[2 * p] - __half2float(h0),
                        v[2 * p + 1] - __half2float(h1));
    }
    *(uint2*)(outHi + (size_t)f * DIM + c * 4) = make_uint2(ph[0], ph[1]);
    *(uint2*)(outLo + (size_t)f * DIM + c * 4) = make_uint2(pl[0], pl[1]);
}

// ===================== HMMA 2-pass fp16 GEMM (3-stage, 2 CTAs/SM) ==========
// out = act(A_full @ fp16(Wt)^T + bias); A given exactly as fp16 hi+lo.
// One barrier per k-chunk: wait -> sync -> issue loads(kc+2) -> compute(kc).
// OUT_MODE 0: relu+bias -> fp16 hi/lo.
// OUT_MODE 2: raw -> f32.
// OUT_MODE 3: relu+bias, then fused head: p12 = relu_tile @ W4_slice (per N-block).
#define ROW_B       80              // 64B data + 16B pad per smem row
#define BUF_BYTES   (128 * ROW_B)   // 10240
#define STG_BYTES   (3 * BUF_BYTES) // 30720 (Ahi, Alo, B)
#define N_STAGES    3
#define PIPE_BYTES  (N_STAGES * STG_BYTES)   // 92160 (>= 67584 epilogue sout)
#define SM_BIAS_OFF PIPE_BYTES
#define SM_W4_OFF   (PIPE_BYTES + 512)
#define SM_TOTAL_G  PIPE_BYTES               // modes 0/2
#define SM_TOTAL_G3 (PIPE_BYTES + 512 + 6144) // mode 3

template <int N_TOTAL, int OUT_MODE>
__global__ void __launch_bounds__(256, 2)
gemm_hmma(const __half* __restrict__ Ahi,
          const __half* __restrict__ Alo,
          const __half* __restrict__ Bw,
          const float* __restrict__ bias,
          void* __restrict__ outHiV, void* __restrict__ outLoV,
          int M,
          const float* __restrict__ W4p, float* __restrict__ p12) {
    extern __shared__ char smem[];
    const uint32_t su = smem_to_u32(smem);
    const int tid = threadIdx.x;
    const int m0 = blockIdx.y * 128;
    const int n0 = blockIdx.x * 128;

    if (OUT_MODE == 3) {
        float* sbias = (float*)(smem + SM_BIAS_OFF);
        float* w4s = (float*)(smem + SM_W4_OFF);
        if (tid < 128) sbias[tid] = bias[n0 + tid];
        for (int i = tid; i < 128 * 12; i += 256)
            w4s[i] = W4p[(size_t)(n0 + i / 12) * 12 + (i % 12)];
    }

    const int lane = tid & 31;
    const int warp = tid >> 5;
    const int wm = warp & 3;   // 4 warps along M
    const int wn = warp >> 2;  // 2 warps along N

    const uint32_t aRow = wm * 32 + (lane & 15);
    const uint32_t aCol = (lane >> 4) * 16;
    const uint32_t bRow = wn * 64 + (lane & 7) + ((lane & 16) >> 1);
    const uint32_t bCol = (lane & 8) ? 16u : 0u;

    const uint32_t aHiB = su + aRow * ROW_B + aCol;                  // buf0
    const uint32_t aLoB = aHiB + BUF_BYTES;                          // buf1
    const uint32_t bB   = su + 2 * BUF_BYTES + bRow * ROW_B + bCol;  // buf2

    const int ldRowHalf = tid >> 2;
    const int ldQ = tid & 3;

    float acc[2][8][4];
#pragma unroll
    for (int t = 0; t < 2; t++)
#pragma unroll
        for (int j = 0; j < 8; j++)
#pragma unroll
            for (int e = 0; e < 4; e++) acc[t][j][e] = 0.0f;

    auto load_stage = [&](int stage, int kc) {
        const int k0 = kc * 32;
        const uint32_t stageBase = (uint32_t)stage * STG_BYTES;
#pragma unroll
        for (int i = 0; i < 6; i++) {
            const int buf = i >> 1;
            const int r = (i & 1) * 64 + ldRowHalf;
            const uint32_t dst = su + stageBase + buf * BUF_BYTES +
                                 r * ROW_B + ldQ * 16;
            const __half* srcp;
            if (buf == 0) {
                int gr = m0 + r; if (gr >= M) gr = M - 1;
                srcp = Ahi + (size_t)gr * DIM + k0 + ldQ * 8;
            } else if (buf == 1) {
                int gr = m0 + r; if (gr >= M) gr = M - 1;
                srcp = Alo + (size_t)gr * DIM + k0 + ldQ * 8;
            } else {
                srcp = Bw + (size_t)(n0 + r) * DIM + k0 + ldQ * 8;
            }
            cp16(dst, srcp);
        }
        asm volatile("cp.async.commit_group;" ::: "memory");
    };

    // prologue: stages 0,1 in flight
    load_stage(0, 0);
    load_stage(1, 1);

    int stage = 0;
    for (int kc = 0; kc < 16; kc++) {
        if (kc == 15) {
            asm volatile("cp.async.wait_group 0;" ::: "memory");
        } else {
            asm volatile("cp.async.wait_group 1;" ::: "memory");
        }
        __syncthreads();   // single barrier: publishes stage kc, frees stage kc-1

        // issue next loads BEFORE compute (into the stage freed by kc-1)
        if (kc + 2 < 16) {
            int ns = stage + 2; if (ns >= N_STAGES) ns -= N_STAGES;
            load_stage(ns, kc + 2);
        }

        const uint32_t sb = (uint32_t)stage * STG_BYTES;
#pragma unroll
        for (int h = 0; h < 2; h++) {
            const uint32_t hoff = sb + h * 32;
            uint32_t ah[2][4], al[2][4];
            ldm_x4(ah[0], aHiB + hoff);
            ldm_x4(ah[1], aHiB + hoff + 16 * ROW_B);
            ldm_x4(al[0], aLoB + hoff);
            ldm_x4(al[1], aLoB + hoff + 16 * ROW_B);
#pragma unroll
            for (int p = 0; p < 4; p++) {
                uint32_t bw[4];
                ldm_x4(bw, bB + hoff + p * (16 * ROW_B));
#pragma unroll
                for (int t = 0; t < 2; t++) {
                    mma_f16(acc[t][2 * p],     ah[t], bw[0], bw[1]);
                    mma_f16(acc[t][2 * p + 1], ah[t], bw[2], bw[3]);
                    mma_f16(acc[t][2 * p],     al[t], bw[0], bw[1]);
                    mma_f16(acc[t][2 * p + 1], al[t], bw[2], bw[3]);
                }
            }
        }
        stage++; if (stage >= N_STAGES) stage = 0;
    }
    __syncthreads();   // all compute done before smem reuse in epilogue

    // -------- epilogue --------
    float* sout = (float*)smem;
    if (OUT_MODE == 3) {
        const float* sbias = (const float*)(smem + SM_BIAS_OFF);
#pragma unroll
        for (int t = 0; t < 2; t++)
#pragma unroll
            for (int j = 0; j < 8; j++) {
                const int row = wm * 32 + t * 16 + (lane >> 2);
                const int col = wn * 64 + j * 8 + (lane & 3) * 2;
                sout[row * 132 + col] =
                    fmaxf(acc[t][j][0] + sbias[col], 0.0f);
                sout[row * 132 + col + 1] =
                    fmaxf(acc[t][j][1] + sbias[col + 1], 0.0f);
                sout[(row + 8) * 132 + col] =
                    fmaxf(acc[t][j][2] + sbias[col], 0.0f);
                sout[(row + 8) * 132 + col + 1] =
                    fmaxf(acc[t][j][3] + sbias[col + 1], 0.0f);
            }
        __syncthreads();
        const float* w4s = (const float*)(smem + SM_W4_OFF);
        const int row = tid >> 1;
        const int jh = (tid & 1) * 6;
        float p[6] = {0, 0, 0, 0, 0, 0};
        for (int c = 0; c < 128; c++) {
            const float h = sout[row * 132 + c];
#pragma unroll
            for (int jj = 0; jj < 6; jj++)
                p[jj] = fmaf(h, w4s[c * 12 + jh + jj], p[jj]);
        }
        const int gr = m0 + row;
        if (gr < M) {
            float* dst = p12 + ((size_t)blockIdx.x * M + gr) * 12 + jh;
#pragma unroll
            for (int jj = 0; jj < 6; jj++) dst[jj] = p[jj];
        }
        return;
    }

#pragma unroll
    for (int t = 0; t < 2; t++)
#pragma unroll
        for (int j = 0; j < 8; j++) {
            const int row = wm * 32 + t * 16 + (lane >> 2);
            const int col = wn * 64 + j * 8 + (lane & 3) * 2;
            sout[row * 132 + col]           = acc[t][j][0];
            sout[row * 132 + col + 1]       = acc[t][j][1];
            sout[(row + 8) * 132 + col]     = acc[t][j][2];
            sout[(row + 8) * 132 + col + 1] = acc[t][j][3];
        }
    __syncthreads();

#pragma unroll
    for (int i = 0; i < 16; i++) {
        const int lin = tid + i * 256;
        const int row = lin >> 5;
        const int q = lin & 31;
        const int gr = m0 + row;
        if (gr >= M) continue;
        float4 v = *(float4*)&sout[row * 132 + q * 4];
        if (OUT_MODE == 0) {
            const float4 bb = __ldg((const float4*)&bias[n0 + q * 4]);
            v.x = fmaxf(v.x + bb.x, 0.0f);
            v.y = fmaxf(v.y + bb.y, 0.0f);
            v.z = fmaxf(v.z + bb.z, 0.0f);
            v.w = fmaxf(v.w + bb.w, 0.0f);
            __half h0 = __float2half_rn(v.x);
            __half h1 = __float2half_rn(v.y);
            __half h2 = __float2half_rn(v.z);
            __half h3 = __float2half_rn(v.w);
            uint2 vh, vl;
            vh.x = (uint32_t)__half_as_ushort(h0) |
                   ((uint32_t)__half_as_ushort(h1) << 16);
            vh.y = (uint32_t)__half_as_ushort(h2) |
                   ((uint32_t)__half_as_ushort(h3) << 16);
            vl.x = pack_h2(v.x - __half2float(h0), v.y - __half2float(h1));
            vl.y = pack_h2(v.z - __half2float(h2), v.w - __half2float(h3));
            const size_t off = (size_t)gr * N_TOTAL + n0 + q * 4;
            *(uint2*)((__half*)outHiV + off) = vh;
            *(uint2*)((__half*)outLoV + off) = vl;
        } else {
            *(float4*)((float*)outHiV + (size_t)gr * N_TOTAL + n0 + q * 4) = v;
        }
    }
}

// ============== analytic 3x3 symmetric eigenvector helpers ==============
__device__ __forceinline__ void cross3(const double a[3], const double b[3],
                                       double c[3]) {
    c[0] = a[1] * b[2] - a[2] * b[1];
    c[1] = a[2] * b[0] - a[0] * b[2];
    c[2] = a[0] * b[1] - a[1] * b[0];
}

__device__ double eigvec3(const double C[6], double lam, double v[3]) {
    double r0[3] = {C[0] - lam, C[3], C[4]};
    double r1[3] = {C[3], C[1] - lam, C[5]};
    double r2[3] = {C[4], C[5], C[2] - lam};
    double c0[3], c1[3], c2[3];
    cross3(r0, r1, c0);
    cross3(r0, r2, c1);
    cross3(r1, r2, c2);
    double n0 = c0[0] * c0[0] + c0[1] * c0[1] + c0[2] * c0[2];
    double n1 = c1[0] * c1[0] + c1[1] * c1[1] + c1[2] * c1[2];
    double n2 = c2[0] * c2[0] + c2[1] * c2[1] + c2[2] * c2[2];
    const double* best = c0;
    double nb = n0;
    if (n1 > nb) { best = c1; nb = n1; }
    if (n2 > nb) { best = c2; nb = n2; }
    if (nb > 0.0) {
        double inv = 1.0 / sqrt(nb);
        v[0] = best[0] * inv; v[1] = best[1] * inv; v[2] = best[2] * inv;
    }
    return nb;
}

__device__ __forceinline__ void arb_perp(const double w[3], double v[3]) {
    if (fabs(w[0]) > 0.5) {
        double inv = 1.0 / sqrt(w[0] * w[0] + w[1] * w[1]);
        v[0] = w[1] * inv; v[1] = -w[0] * inv; v[2] = 0.0;
    } else {
        double inv = 1.0 / sqrt(w[1] * w[1] + w[2] * w[2]);
        v[0] = 0.0; v[1] = w[2] * inv; v[2] = -w[1] * inv;
    }
}

// ===================== procrustes (analytic) + transform + scatter ==========
__global__ void procrustes_kernel(const float* __restrict__ p12,
                                  const float* __restrict__ b4,
                                  const float* __restrict__ verts,
                                  const int* __restrict__ faces,
                                  float* __restrict__ out_trans,
                                  float* __restrict__ out_rot) {
    int f = blockIdx.x * blockDim.x + threadIdx.x;
    if (f >= N_FACES) return;

    const size_t HALF = (size_t)N_FACES * 12;
    float o12[12];
#pragma unroll
    for (int j = 0; j < 12; j++)
        o12[j] = p12[(size_t)f * 12 + j] + p12[HALF + (size_t)f * 12 + j] +
                 __ldg(&b4[j]);

    double Mm[3][3];
#pragma unroll
    for (int i = 0; i < 3; i++)
#pragma unroll
        for (int j = 0; j < 3; j++)
            Mm[i][j] = (double)o12[i * 3 + j];

    double C[6];
    C[0] = Mm[0][0] * Mm[0][0] + Mm[1][0] * Mm[1][0] + Mm[2][0] * Mm[2][0];
    C[1] = Mm[0][1] * Mm[0][1] + Mm[1][1] * Mm[1][1] + Mm[2][1] * Mm[2][1];
    C[2] = Mm[0][2] * Mm[0][2] + Mm[1][2] * Mm[1][2] + Mm[2][2] * Mm[2][2];
    C[3] = Mm[0][0] * Mm[0][1] + Mm[1][0] * Mm[1][1] + Mm[2][0] * Mm[2][1];
    C[4] = Mm[0][0] * Mm[0][2] + Mm[1][0] * Mm[1][2] + Mm[2][0] * Mm[2][2];
    C[5] = Mm[0][1] * Mm[0][2] + Mm[1][1] * Mm[1][2] + Mm[2][1] * Mm[2][2];

    double v1[3], v2[3], v3[3];
    double mtr = (C[0] + C[1] + C[2]) * (1.0 / 3.0);
    double K0 = C[0] - mtr, K1 = C[1] - mtr, K2 = C[2] - mtr;
    double p2 = K0 * K0 + K1 * K1 + K2 * K2 +
                2.0 * (C[3] * C[3] + C[4] * C[4] + C[5] * C[5]);
    double p = p2 * (1.0 / 6.0);
    double sp = sqrt(p);

    bool ident = (sp < 1e-100 + 1e-14 * fabs(mtr));
    if (ident) {
        v1[0] = 1; v1[1] = 0; v1[2] = 0;
        v2[0] = 0; v2[1] = 1; v2[2] = 0;
        v3[0] = 0; v3[1] = 0; v3[2] = 1;
    } else {
        double detK = K0 * (K1 * K2 - C[5] * C[5])
                    - C[3] * (C[3] * K2 - C[5] * C[4])
                    + C[4] * (C[3] * C[5] - K1 * C[4]);
        double r = detK / (2.0 * sp * sp * sp);
        r = fmin(1.0, fmax(-1.0, r));
        float phi = acosf((float)r) * (1.0f / 3.0f);
        double lam1 = mtr + 2.0 * sp * (double)cosf(phi);
        double lam3 = mtr + 2.0 * sp * (double)cosf(phi + 2.0943951023931953f);

        const double thr = 1e-24 * p2 * p2;
        double n1 = eigvec3(C, lam1, v1);
        double n3 = eigvec3(C, lam3, v3);
        if (n1 > thr && n3 > thr) {
            cross3(v3, v1, v2);
            double inv = 1.0 / sqrt(v2[0] * v2[0] + v2[1] * v2[1] + v2[2] * v2[2]);
            v2[0] *= inv; v2[1] *= inv; v2[2] *= inv;
        } else if (n3 > thr) {
            arb_perp(v3, v1);
            cross3(v3, v1, v2);
        } else if (n1 > thr) {
            arb_perp(v1, v3);
            cross3(v3, v1, v2);
        } else {
            v1[0] = 1; v1[1] = 0; v1[2] = 0;
            v2[0] = 0; v2[1] = 1; v2[2] = 0;
            v3[0] = 0; v3[1] = 0; v3[2] = 1;
        }
    }

    double b1c[3], b2c[3];
#pragma unroll
    for (int i = 0; i < 3; i++) {
        b1c[i] = Mm[i][0] * v1[0] + Mm[i][1] * v1[1] + Mm[i][2] * v1[2];
        b2c[i] = Mm[i][0] * v2[0] + Mm[i][1] * v2[1] + Mm[i][2] * v2[2];
    }

    double u1[3], u2[3], u3[3];
    double nb1 = sqrt(b1c[0] * b1c[0] + b1c[1] * b1c[1] + b1c[2] * b1c[2]);
    double in1 = 1.0 / fmax(nb1, 1e-150);
#pragma unroll
    for (int i = 0; i < 3; i++) u1[i] = b1c[i] * in1;
    double d12 = u1[0] * b2c[0] + u1[1] * b2c[1] + u1[2] * b2c[2];
    double w[3];
#pragma unroll
    for (int i = 0; i < 3; i++) w[i] = b2c[i] - d12 * u1[i];
    double nb2 = sqrt(w[0] * w[0] + w[1] * w[1] + w[2] * w[2]);
    double in2 = 1.0 / fmax(nb2, 1e-150);
#pragma unroll
    for (int i = 0; i < 3; i++) u2[i] = w[i] * in2;
    u3[0] = u1[1] * u2[2] - u1[2] * u2[1];
    u3[1] = u1[2] * u2[0] - u1[0] * u2[2];
    u3[2] = u1[0] * u2[1] - u1[1] * u2[0];

    float R[3][3];
#pragma unroll
    for (int i = 0; i < 3; i++) {
        R[i][0] = (float)(u1[i] * v1[0] + u2[i] * v2[0] + u3[i] * v3[0]);
        R[i][1] = (float)(u1[i] * v1[1] + u2[i] * v2[1] + u3[i] * v3[1]);
        R[i][2] = (float)(u1[i] * v1[2] + u2[i] * v2[2] + u3[i] * v3[2]);
    }

#pragma unroll
    for (int i = 0; i < 3; i++)
#pragma unroll
        for (int j = 0; j < 3; j++)
            out_rot[(size_t)f * 9 + i * 3 + j] = R[i][j];

    float t0 = o12[9];
    float t1 = o12[10];
    float t2 = o12[11];

#pragma unroll
    for (int c = 0; c < 3; c++) {
        int vi = faces[f * 3 + c];
        float vx = verts[(size_t)vi * 3 + 0];
        float vy = verts[(size_t)vi * 3 + 1];
        float vz = verts[(size_t)vi * 3 + 2];
        float tvx = vx * R[0][0] + vy * R[1][0] + vz * R[2][0] + t0;
        float tvy = vx * R[0][1] + vy * R[1][1] + vz * R[2][1] + t1;
        float tvz = vx * R[0][2] + vy * R[1][2] + vz * R[2][2] + t2;
        out_trans[(size_t)f * 9 + c * 3 + 0] = tvx;
        out_trans[(size_t)f * 9 + c * 3 + 1] = tvy;
        out_trans[(size_t)f * 9 + c * 3 + 2] = tvz;
        atomicAdd(&g_sum[vi * 3 + 0], tvx);
        atomicAdd(&g_sum[vi * 3 + 1], tvy);
        atomicAdd(&g_sum[vi * 3 + 2], tvz);
        atomicAdd(&g_cnt[vi], 1.0f);
    }
}

// ===================== finalize segment mean =====================
__global__ void finalize_kernel(float* __restrict__ out_vfeat) {
    int v = blockIdx.x * blockDim.x + threadIdx.x;
    if (v >= N_VERTS) return;
    float c = fmaxf(g_cnt[v], 1.0f);
    float inv = 1.0f / c;
    out_vfeat[v * 3 + 0] = g_sum[v * 3 + 0] * inv;
    out_vfeat[v * 3 + 1] = g_sum[v * 3 + 1] * inv;
    out_vfeat[v * 3 + 2] = g_sum[v * 3 + 2] * inv;
}

// ===================== launch =====================
extern "C" void kernel_launch(void* const* d_in, const int* in_sizes, int n_in,
                              void* d_out, int out_size) {
    const float* verts    = (const float*)d_in[0];
    const float* features = (const float*)d_in[1];
    const int*   faces    = (const int*)d_in[2];
    const float* W1 = (const float*)d_in[3];
    const float* b1 = (const float*)d_in[4];
    const float* W2 = (const float*)d_in[5];
    const float* b2 = (const float*)d_in[6];
    const float* W3 = (const float*)d_in[7];
    const float* b3 = (const float*)d_in[8];
    const float* W4 = (const float*)d_in[9];
    const float* b4 = (const float*)d_in[10];

    float* out = (float*)d_out;
    float* out_vfeat = out;
    float* out_trans = out + (size_t)N_VERTS * 3;
    float* out_rot   = out_trans + (size_t)N_FACES * 9;

    __half *p_f_hi, *p_f_lo, *p_x_hi, *p_x_lo, *p_y_hi, *p_y_lo;
    __half *p_w1t, *p_w2t, *p_w3t;
    float *p_G, *p_p12;
    cudaGetSymbolAddress((void**)&p_f_hi, g_f_hi);
    cudaGetSymbolAddress((void**)&p_f_lo, g_f_lo);
    cudaGetSymbolAddress((void**)&p_G, g_G);
    cudaGetSymbolAddress((void**)&p_x_hi, g_x_hi);
    cudaGetSymbolAddress((void**)&p_x_lo, g_x_lo);
    cudaGetSymbolAddress((void**)&p_y_hi, g_y_hi);
    cudaGetSymbolAddress((void**)&p_y_lo, g_y_lo);
    cudaGetSymbolAddress((void**)&p_w1t, g_w1t);
    cudaGetSymbolAddress((void**)&p_w2t, g_w2t);
    cudaGetSymbolAddress((void**)&p_w3t, g_w3t);
    cudaGetSymbolAddress((void**)&p_p12, g_p12);

    cudaFuncSetAttribute(gemm_hmma<512, 0>,
                         cudaFuncAttributeMaxDynamicSharedMemorySize, SM_TOTAL_G);
    cudaFuncSetAttribute(gemm_hmma<512, 2>,
                         cudaFuncAttributeMaxDynamicSharedMemorySize, SM_TOTAL_G);
    cudaFuncSetAttribute(gemm_hmma<256, 3>,
                         cudaFuncAttributeMaxDynamicSharedMemorySize, SM_TOTAL_G3);

    // 1. prep: zero accumulators + convert weights + split features (1 launch)
    prep_kernel<<<(PREP_FEAT + 255) / 256, 256>>>(W1, W2, W3, features);

    // 2. G = features @ W1  (M = N_VERTS, raw f32 out)
    {
        dim3 blk(256);
        dim3 gG(4, (N_VERTS + 127) / 128);
        gemm_hmma<512, 2><<<gG, blk, SM_TOTAL_G>>>(p_f_hi, p_f_lo, p_w1t,
                                                   nullptr, p_G, nullptr, N_VERTS,
                                                   nullptr, nullptr);
    }

    // 3. h1 = relu(mean(G rows) + b1) -> fp16 split (per-face)
    gather_relu_split_kernel<<<N_FACES, 128>>>(p_G, faces, b1, p_x_hi, p_x_lo);

    // 4. layer 2; layer 3 fused with W4 head -> partial out12
    {
        dim3 blk(256);
        dim3 g12(4, (N_FACES + 127) / 128);
        gemm_hmma<512, 0><<<g12, blk, SM_TOTAL_G>>>(p_x_hi, p_x_lo, p_w2t,
                                                    b2, p_y_hi, p_y_lo, N_FACES,
                                                    nullptr, nullptr);
        dim3 g3(2, (N_FACES + 127) / 128);
        gemm_hmma<256, 3><<<g3, blk, SM_TOTAL_G3>>>(p_y_hi, p_y_lo, p_w3t,
                                                    b3, nullptr, nullptr, N_FACES,
                                                    W4, p_p12);
    }

    // 5. procrustes (analytic eigensolver) + transform + scatter
    procrustes_kernel<<<(N_FACES + 255) / 256, 256>>>(p_p12, b4, verts, faces,
                                                      out_trans, out_rot);

    // 6. segment mean
    finalize_kernel<<<(N_VERTS + 255) / 256, 256>>>(out_vfeat);
}

// round 15
// speedup vs baseline: 1.0725x; 1.0652x over previous
#include <cuda_runtime.h>
#include <cuda_fp16.h>
#include <math.h>
#include <stdint.h>

#define N_VERTS 100000
#define N_FACES 200000
#define DIM 512

// ===================== portable PTX helpers (sm_80+) =====================
__device__ __forceinline__ uint32_t smem_to_u32(const void* smem_ptr) {
    uint32_t addr;
    asm("{ .reg .u64 tmp; cvta.to.shared.u64 tmp, %1; cvt.u32.u64 %0, tmp; }"
        : "=r"(addr) : "l"(smem_ptr));
    return addr;
}

__device__ __forceinline__ void cp16(uint32_t dst, const void* src) {
    asm volatile("cp.async.cg.shared.global [%0], [%1], 16;"
                 :: "r"(dst), "l"(src) : "memory");
}

__device__ __forceinline__ void ldm_x4(uint32_t (&r)[4], uint32_t addr) {
    asm volatile("ldmatrix.sync.aligned.m8n8.x4.shared.b16 {%0,%1,%2,%3}, [%4];"
                 : "=r"(r[0]), "=r"(r[1]), "=r"(r[2]), "=r"(r[3]) : "r"(addr));
}

__device__ __forceinline__ void mma_f16(float (&d)[4], const uint32_t (&a)[4],
                                        uint32_t b0, uint32_t b1) {
    asm volatile(
        "mma.sync.aligned.m16n8k16.row.col.f32.f16.f16.f32 "
        "{%0,%1,%2,%3}, {%4,%5,%6,%7}, {%8,%9}, {%0,%1,%2,%3};"
        : "+f"(d[0]), "+f"(d[1]), "+f"(d[2]), "+f"(d[3])
        : "r"(a[0]), "r"(a[1]), "r"(a[2]), "r"(a[3]), "r"(b0), "r"(b1));
}

__device__ __forceinline__ uint32_t pack_h2(float a, float b) {
    __half2 t = __floats2half2_rn(a, b);
    return *(uint32_t*)&t;
}

// ===================== scratch (no allocations allowed) =====================
__device__ __half g_f_hi[(size_t)N_VERTS * DIM];   // split features
__device__ __half g_f_lo[(size_t)N_VERTS * DIM];
__device__ float  g_G[(size_t)N_VERTS * DIM];      // features @ W1
__device__ __half g_x_hi[(size_t)N_FACES * DIM];
__device__ __half g_x_lo[(size_t)N_FACES * DIM];
__device__ __half g_y_hi[(size_t)N_FACES * DIM];
__device__ __half g_y_lo[(size_t)N_FACES * DIM];
__device__ float  g_p12[2 * (size_t)N_FACES * 12]; // partial out12 per N-block
__device__ float  g_sum[N_VERTS * 3];
__device__ float  g_cnt[N_VERTS];
// transposed fp16 weights: Wt[n][k] = fp16(W[k][n])
__device__ __half g_w1t[DIM * DIM];
__device__ __half g_w2t[DIM * DIM];
__device__ __half g_w3t[256 * DIM];

// ====== prep: zero accumulators + convert all weights + split features =====
#define PREP_W1   262144              // 512*512
#define PREP_W2   524288
#define PREP_W3   655360              // + 512*256
#define PREP_SUM  955360              // + 300000
#define PREP_CNT  1055360             // + 100000
#define PREP_FEAT (PREP_CNT + N_VERTS * 128)  // + 12,800,000 (f4 slots)

__global__ void prep_kernel(const float* __restrict__ W1,
                            const float* __restrict__ W2,
                            const float* __restrict__ W3,
                            const float* __restrict__ features) {
    int id = blockIdx.x * blockDim.x + threadIdx.x;
    if (id < PREP_W1) {
        int k = id / 512, n = id % 512;
        g_w1t[(size_t)n * DIM + k] = __float2half_rn(W1[id]);
    } else if (id < PREP_W2) {
        int i = id - PREP_W1;
        int k = i / 512, n = i % 512;
        g_w2t[(size_t)n * DIM + k] = __float2half_rn(W2[i]);
    } else if (id < PREP_W3) {
        int i = id - PREP_W2;
        int k = i / 256, n = i % 256;
        g_w3t[(size_t)n * DIM + k] = __float2half_rn(W3[i]);
    } else if (id < PREP_SUM) {
        g_sum[id - PREP_W3] = 0.0f;
    } else if (id < PREP_CNT) {
        g_cnt[id - PREP_SUM] = 0.0f;
    } else if (id < PREP_FEAT) {
        int i = id - PREP_CNT;          // 0 .. N_VERTS*128-1
        int r = i >> 7;                 // vertex row
        int c = i & 127;                // float4 column
        float4 x = ((const float4*)(features + (size_t)r * DIM))[c];
        float v[4] = {x.x, x.y, x.z, x.w};
        uint32_t ph[2], pl[2];
#pragma unroll
        for (int p = 0; p < 2; p++) {
            __half h0 = __float2half_rn(v[2 * p]);
            __half h1 = __float2half_rn(v[2 * p + 1]);
            ph[p] = (uint32_t)__half_as_ushort(h0) |
                    ((uint32_t)__half_as_ushort(h1) << 16);
            pl[p] = pack_h2(v[2 * p] - __half2float(h0),
                            v[2 * p + 1] - __half2float(h1));
        }
        *(uint2*)(g_f_hi + (size_t)r * DIM + c * 4) = make_uint2(ph[0], ph[1]);
        *(uint2*)(g_f_lo + (size_t)r * DIM + c * 4) = make_uint2(pl[0], pl[1]);
    }
}

// ===================== gather G rows + mean + bias + relu + split ==========
__global__ void gather_relu_split_kernel(const float* __restrict__ G,
                                         const int* __restrict__ faces,
                                         const float* __restrict__ b1,
                                         __half* __restrict__ outHi,
                                         __half* __restrict__ outLo) {
    int f = blockIdx.x;
    int c = threadIdx.x;  // 128 threads x float4
    int i0 = faces[f * 3 + 0];
    int i1 = faces[f * 3 + 1];
    int i2 = faces[f * 3 + 2];
    float4 a = ((const float4*)(G + (size_t)i0 * DIM))[c];
    float4 b = ((const float4*)(G + (size_t)i1 * DIM))[c];
    float4 d = ((const float4*)(G + (size_t)i2 * DIM))[c];
    float4 bb = __ldg((const float4*)&b1[c * 4]);
    const float k3 = 1.0f / 3.0f;
    float v[4];
    v[0] = fmaxf(fmaf(a.x + b.x + d.x, k3, bb.x), 0.0f);
    v[1] = fmaxf(fmaf(a.y + b.y + d.y, k3, bb.y), 0.0f);
    v[2] = fmaxf(fmaf(a.z + b.z + d.z, k3, bb.z), 0.0f);
    v[3] = fmaxf(fmaf(a.w + b.w + d.w, k3, bb.w), 0.0f);
    uint32_t ph[2], pl[2];
#pragma unroll
    for (int p = 0; p < 2; p++) {
        __half h0 = __float2half_rn(v[2 * p]);
        __half h1 = __float2half_rn(v[2 * p + 1]);
        ph[p] = (uint32_t)__half_as_ushort(h0) |
                ((uint32_t)__half_as_ushort(h1) << 16);
        pl[p] = pack_h2(v[2 * p] - __half2float(h0),
                        v[2 * p + 1] - __half2float(h1));
    }
    *(uint2*)(outHi + (size_t)f * DIM + c * 4) = make_uint2(ph[0], ph[1]);
    *(uint2*)(outLo + (size_t)f * DIM + c * 4) = make_uint2(pl[0], pl[1]);
}

// ===================== HMMA 2-pass fp16 GEMM (BK=64, 2-stage, 2 CTAs/SM) ===
// out = act(A_full @ fp16(Wt)^T + bias); A given exactly as fp16 hi+lo.
// OUT_MODE 0: relu+bias -> fp16 hi/lo.
// OUT_MODE 2: raw -> f32.
// OUT_MODE 3: relu+bias, then fused head: p12 = relu_tile @ W4_slice (per N-block).
#define ROW_B       144             // 128B data + 16B pad per smem row
#define BUF_BYTES   (128 * ROW_B)   // 18432
#define STG_BYTES   (3 * BUF_BYTES) // 55296 (Ahi, Alo, B)
#define PIPE_BYTES  (2 * STG_BYTES) // 110592 (>= 67584 epilogue sout)
// mode-3 epilogue scratch lives ABOVE sout, inside PIPE_BYTES:
#define SM_BIAS_OFF 67584
#define SM_W4_OFF   (67584 + 512)   // + 6144 = 74240 <= 110592
#define SM_TOTAL_G  PIPE_BYTES

template <int N_TOTAL, int OUT_MODE>
__global__ void __launch_bounds__(256, 2)
gemm_hmma(const __half* __restrict__ Ahi,
          const __half* __restrict__ Alo,
          const __half* __restrict__ Bw,
          const float* __restrict__ bias,
          void* __restrict__ outHiV, void* __restrict__ outLoV,
          int M,
          const float* __restrict__ W4p, float* __restrict__ p12) {
    extern __shared__ char smem[];
    const uint32_t su = smem_to_u32(smem);
    const int tid = threadIdx.x;
    const int m0 = blockIdx.y * 128;
    const int n0 = blockIdx.x * 128;

    const int lane = tid & 31;
    const int warp = tid >> 5;
    const int wm = warp & 3;   // 4 warps along M
    const int wn = warp >> 2;  // 2 warps along N

    const uint32_t aRow = wm * 32 + (lane & 15);
    const uint32_t aCol = (lane >> 4) * 16;
    const uint32_t bRow = wn * 64 + (lane & 7) + ((lane & 16) >> 1);
    const uint32_t bCol = (lane & 8) ? 16u : 0u;

    const uint32_t aHiB = su + aRow * ROW_B + aCol;                  // buf0
    const uint32_t aLoB = aHiB + BUF_BYTES;                          // buf1
    const uint32_t bB   = su + 2 * BUF_BYTES + bRow * ROW_B + bCol;  // buf2

    const int ldRow = tid >> 3;     // 0..31
    const int ldQ = tid & 7;        // 8 x 16B = 128B data per row

    float acc[2][8][4];
#pragma unroll
    for (int t = 0; t < 2; t++)
#pragma unroll
        for (int j = 0; j < 8; j++)
#pragma unroll
            for (int e = 0; e < 4; e++) acc[t][j][e] = 0.0f;

    auto load_stage = [&](int stage, int kc) {
        const int k0 = kc * 64;
        const uint32_t stageBase = (uint32_t)stage * STG_BYTES;
#pragma unroll
        for (int i = 0; i < 12; i++) {
            const int buf = i >> 2;          // 0..2
            const int r = (i & 3) * 32 + ldRow;
            const uint32_t dst = su + stageBase + buf * BUF_BYTES +
                                 r * ROW_B + ldQ * 16;
            const __half* srcp;
            if (buf == 0) {
                int gr = m0 + r; if (gr >= M) gr = M - 1;
                srcp = Ahi + (size_t)gr * DIM + k0 + ldQ * 8;
            } else if (buf == 1) {
                int gr = m0 + r; if (gr >= M) gr = M - 1;
                srcp = Alo + (size_t)gr * DIM + k0 + ldQ * 8;
            } else {
                srcp = Bw + (size_t)(n0 + r) * DIM + k0 + ldQ * 8;
            }
            cp16(dst, srcp);
        }
        asm volatile("cp.async.commit_group;" ::: "memory");
    };

    // prologue: both stages in flight
    load_stage(0, 0);
    load_stage(1, 1);

    for (int kc = 0; kc < 8; kc++) {
        if (kc == 7) {
            asm volatile("cp.async.wait_group 0;" ::: "memory");
        } else {
            asm volatile("cp.async.wait_group 1;" ::: "memory");
        }
        __syncthreads();

        const uint32_t sb = (uint32_t)(kc & 1) * STG_BYTES;
#pragma unroll
        for (int h = 0; h < 4; h++) {       // 4 x k16 subchunks (32B apart)
            const uint32_t hoff = sb + h * 32;
            uint32_t ah[2][4], al[2][4];
            ldm_x4(ah[0], aHiB + hoff);
            ldm_x4(ah[1], aHiB + hoff + 16 * ROW_B);
            ldm_x4(al[0], aLoB + hoff);
            ldm_x4(al[1], aLoB + hoff + 16 * ROW_B);
#pragma unroll
            for (int p = 0; p < 4; p++) {
                uint32_t bw[4];
                ldm_x4(bw, bB + hoff + p * (16 * ROW_B));
#pragma unroll
                for (int t = 0; t < 2; t++) {
                    mma_f16(acc[t][2 * p],     ah[t], bw[0], bw[1]);
                    mma_f16(acc[t][2 * p + 1], ah[t], bw[2], bw[3]);
                    mma_f16(acc[t][2 * p],     al[t], bw[0], bw[1]);
                    mma_f16(acc[t][2 * p + 1], al[t], bw[2], bw[3]);
                }
            }
        }
        __syncthreads();
        if (kc + 2 < 8) load_stage(kc & 1, kc + 2);
    }
    __syncthreads();   // ensure all compute done before smem reuse

    // -------- epilogue --------
    float* sout = (float*)smem;
    if (OUT_MODE == 3) {
        // load bias + W4 slice into smem above sout (stages no longer needed)
        float* sbias = (float*)(smem + SM_BIAS_OFF);
        float* w4s = (float*)(smem + SM_W4_OFF);
        if (tid < 128) sbias[tid] = bias[n0 + tid];
        for (int i = tid; i < 128 * 12; i += 256)
            w4s[i] = W4p[(size_t)(n0 + i / 12) * 12 + (i % 12)];
        __syncthreads();
#pragma unroll
        for (int t = 0; t < 2; t++)
#pragma unroll
            for (int j = 0; j < 8; j++) {
                const int row = wm * 32 + t * 16 + (lane >> 2);
                const int col = wn * 64 + j * 8 + (lane & 3) * 2;
                sout[row * 132 + col] =
                    fmaxf(acc[t][j][0] + sbias[col], 0.0f);
                sout[row * 132 + col + 1] =
                    fmaxf(acc[t][j][1] + sbias[col + 1], 0.0f);
                sout[(row + 8) * 132 + col] =
                    fmaxf(acc[t][j][2] + sbias[col], 0.0f);
                sout[(row + 8) * 132 + col + 1] =
                    fmaxf(acc[t][j][3] + sbias[col + 1], 0.0f);
            }
        __syncthreads();
        const int row = tid >> 1;
        const int jh = (tid & 1) * 6;
        float p[6] = {0, 0, 0, 0, 0, 0};
        for (int c = 0; c < 128; c++) {
            const float h = sout[row * 132 + c];
#pragma unroll
            for (int jj = 0; jj < 6; jj++)
                p[jj] = fmaf(h, w4s[c * 12 + jh + jj], p[jj]);
        }
        const int gr = m0 + row;
        if (gr < M) {
            float* dst = p12 + ((size_t)blockIdx.x * M + gr) * 12 + jh;
#pragma unroll
            for (int jj = 0; jj < 6; jj++) dst[jj] = p[jj];
        }
        return;
    }

#pragma unroll
    for (int t = 0; t < 2; t++)
#pragma unroll
        for (int j = 0; j < 8; j++) {
            const int row = wm * 32 + t * 16 + (lane >> 2);
            const int col = wn * 64 + j * 8 + (lane & 3) * 2;
            sout[row * 132 + col]           = acc[t][j][0];
            sout[row * 132 + col + 1]       = acc[t][j][1];
            sout[(row + 8) * 132 + col]     = acc[t][j][2];
            sout[(row + 8) * 132 + col + 1] = acc[t][j][3];
        }
    __syncthreads();

#pragma unroll
    for (int i = 0; i < 16; i++) {
        const int lin = tid + i * 256;
        const int row = lin >> 5;
        const int q = lin & 31;
        const int gr = m0 + row;
        if (gr >= M) continue;
        float4 v = *(float4*)&sout[row * 132 + q * 4];
        if (OUT_MODE == 0) {
            const float4 bb = __ldg((const float4*)&bias[n0 + q * 4]);
            v.x = fmaxf(v.x + bb.x, 0.0f);
            v.y = fmaxf(v.y + bb.y, 0.0f);
            v.z = fmaxf(v.z + bb.z, 0.0f);
            v.w = fmaxf(v.w + bb.w, 0.0f);
            __half h0 = __float2half_rn(v.x);
            __half h1 = __float2half_rn(v.y);
            __half h2 = __float2half_rn(v.z);
            __half h3 = __float2half_rn(v.w);
            uint2 vh, vl;
            vh.x = (uint32_t)__half_as_ushort(h0) |
                   ((uint32_t)__half_as_ushort(h1) << 16);
            vh.y = (uint32_t)__half_as_ushort(h2) |
                   ((uint32_t)__half_as_ushort(h3) << 16);
            vl.x = pack_h2(v.x - __half2float(h0), v.y - __half2float(h1));
            vl.y = pack_h2(v.z - __half2float(h2), v.w - __half2float(h3));
            const size_t off = (size_t)gr * N_TOTAL + n0 + q * 4;
            *(uint2*)((__half*)outHiV + off) = vh;
            *(uint2*)((__half*)outLoV + off) = vl;
        } else {
            *(float4*)((float*)outHiV + (size_t)gr * N_TOTAL + n0 + q * 4) = v;
        }
    }
}

// ============== analytic 3x3 symmetric eigenvector helpers ==============
__device__ __forceinline__ void cross3(const double a[3], const double b[3],
                                       double c[3]) {
    c[0] = a[1] * b[2] - a[2] * b[1];
    c[1] = a[2] * b[0] - a[0] * b[2];
    c[2] = a[0] * b[1] - a[1] * b[0];
}

__device__ double eigvec3(const double C[6], double lam, double v[3]) {
    double r0[3] = {C[0] - lam, C[3], C[4]};
    double r1[3] = {C[3], C[1] - lam, C[5]};
    double r2[3] = {C[4], C[5], C[2] - lam};
    double c0[3], c1[3], c2[3];
    cross3(r0, r1, c0);
    cross3(r0, r2, c1);
    cross3(r1, r2, c2);
    double n0 = c0[0] * c0[0] + c0[1] * c0[1] + c0[2] * c0[2];
    double n1 = c1[0] * c1[0] + c1[1] * c1[1] + c1[2] * c1[2];
    double n2 = c2[0] * c2[0] + c2[1] * c2[1] + c2[2] * c2[2];
    const double* best = c0;
    double nb = n0;
    if (n1 > nb) { best = c1; nb = n1; }
    if (n2 > nb) { best = c2; nb = n2; }
    if (nb > 0.0) {
        double inv = 1.0 / sqrt(nb);
        v[0] = best[0] * inv; v[1] = best[1] * inv; v[2] = best[2] * inv;
    }
    return nb;
}

__device__ __forceinline__ void arb_perp(const double w[3], double v[3]) {
    if (fabs(w[0]) > 0.5) {
        double inv = 1.0 / sqrt(w[0] * w[0] + w[1] * w[1]);
        v[0] = w[1] * inv; v[1] = -w[0] * inv; v[2] = 0.0;
    } else {
        double inv = 1.0 / sqrt(w[1] * w[1] + w[2] * w[2]);
        v[0] = 0.0; v[1] = w[2] * inv; v[2] = -w[1] * inv;
    }
}

// ===================== procrustes (analytic) + transform + scatter ==========
__global__ void procrustes_kernel(const float* __restrict__ p12,
                                  const float* __restrict__ b4,
                                  const float* __restrict__ verts,
                                  const int* __restrict__ faces,
                                  float* __restrict__ out_trans,
                                  float* __restrict__ out_rot) {
    int f = blockIdx.x * blockDim.x + threadIdx.x;
    if (f >= N_FACES) return;

    const size_t HALF = (size_t)N_FACES * 12;
    float o12[12];
#pragma unroll
    for (int j = 0; j < 12; j++)
        o12[j] = p12[(size_t)f * 12 + j] + p12[HALF + (size_t)f * 12 + j] +
                 __ldg(&b4[j]);

    double Mm[3][3];
#pragma unroll
    for (int i = 0; i < 3; i++)
#pragma unroll
        for (int j = 0; j < 3; j++)
            Mm[i][j] = (double)o12[i * 3 + j];

    double C[6];
    C[0] = Mm[0][0] * Mm[0][0] + Mm[1][0] * Mm[1][0] + Mm[2][0] * Mm[2][0];
    C[1] = Mm[0][1] * Mm[0][1] + Mm[1][1] * Mm[1][1] + Mm[2][1] * Mm[2][1];
    C[2] = Mm[0][2] * Mm[0][2] + Mm[1][2] * Mm[1][2] + Mm[2][2] * Mm[2][2];
    C[3] = Mm[0][0] * Mm[0][1] + Mm[1][0] * Mm[1][1] + Mm[2][0] * Mm[2][1];
    C[4] = Mm[0][0] * Mm[0][2] + Mm[1][0] * Mm[1][2] + Mm[2][0] * Mm[2][2];
    C[5] = Mm[0][1] * Mm[0][2] + Mm[1][1] * Mm[1][2] + Mm[2][1] * Mm[2][2];

    double v1[3], v2[3], v3[3];
    double mtr = (C[0] + C[1] + C[2]) * (1.0 / 3.0);
    double K0 = C[0] - mtr, K1 = C[1] - mtr, K2 = C[2] - mtr;
    double p2 = K0 * K0 + K1 * K1 + K2 * K2 +
                2.0 * (C[3] * C[3] + C[4] * C[4] + C[5] * C[5]);
    double p = p2 * (1.0 / 6.0);
    double sp = sqrt(p);

    bool ident = (sp < 1e-100 + 1e-14 * fabs(mtr));
    if (ident) {
        v1[0] = 1; v1[1] = 0; v1[2] = 0;
        v2[0] = 0; v2[1] = 1; v2[2] = 0;
        v3[0] = 0; v3[1] = 0; v3[2] = 1;
    } else {
        double detK = K0 * (K1 * K2 - C[5] * C[5])
                    - C[3] * (C[3] * K2 - C[5] * C[4])
                    + C[4] * (C[3] * C[5] - K1 * C[4]);
        double r = detK / (2.0 * sp * sp * sp);
        r = fmin(1.0, fmax(-1.0, r));
        float phi = acosf((float)r) * (1.0f / 3.0f);
        double lam1 = mtr + 2.0 * sp * (double)cosf(phi);
        double lam3 = mtr + 2.0 * sp * (double)cosf(phi + 2.0943951023931953f);

        const double thr = 1e-24 * p2 * p2;
        double n1 = eigvec3(C, lam1, v1);
        double n3 = eigvec3(C, lam3, v3);
        if (n1 > thr && n3 > thr) {
            cross3(v3, v1, v2);
            double inv = 1.0 / sqrt(v2[0] * v2[0] + v2[1] * v2[1] + v2[2] * v2[2]);
            v2[0] *= inv; v2[1] *= inv; v2[2] *= inv;
        } else if (n3 > thr) {
            arb_perp(v3, v1);
            cross3(v3, v1, v2);
        } else if (n1 > thr) {
            arb_perp(v1, v3);
            cross3(v3, v1, v2);
        } else {
            v1[0] = 1; v1[1] = 0; v1[2] = 0;
            v2[0] = 0; v2[1] = 1; v2[2] = 0;
            v3[0] = 0; v3[1] = 0; v3[2] = 1;
        }
    }

    double b1c[3], b2c[3];
#pragma unroll
    for (int i = 0; i < 3; i++) {
        b1c[i] = Mm[i][0] * v1[0] + Mm[i][1] * v1[1] + Mm[i][2] * v1[2];
        b2c[i] = Mm[i][0] * v2[0] + Mm[i][1] * v2[1] + Mm[i][2] * v2[2];
    }

    double u1[3], u2[3], u3[3];
    double nb1 = sqrt(b1c[0] * b1c[0] + b1c[1] * b1c[1] + b1c[2] * b1c[2]);
    double in1 = 1.0 / fmax(nb1, 1e-150);
#pragma unroll
    for (int i = 0; i < 3; i++) u1[i] = b1c[i] * in1;
    double d12 = u1[0] * b2c[0] + u1[1] * b2c[1] + u1[2] * b2c[2];
    double w[3];
#pragma unroll
    for (int i = 0; i < 3; i++) w[i] = b2c[i] - d12 * u1[i];
    double nb2 = sqrt(w[0] * w[0] + w[1] * w[1] + w[2] * w[2]);
    double in2 = 1.0 / fmax(nb2, 1e-150);
#pragma unroll
    for (int i = 0; i < 3; i++) u2[i] = w[i] * in2;
    u3[0] = u1[1] * u2[2] - u1[2] * u2[1];
    u3[1] = u1[2] * u2[0] - u1[0] * u2[2];
    u3[2] = u1[0] * u2[1] - u1[1] * u2[0];

    float R[3][3];
#pragma unroll
    for (int i = 0; i < 3; i++) {
        R[i][0] = (float)(u1[i] * v1[0] + u2[i] * v2[0] + u3[i] * v3[0]);
        R[i][1] = (float)(u1[i] * v1[1] + u2[i] * v2[1] + u3[i] * v3[1]);
        R[i][2] = (float)(u1[i] * v1[2] + u2[i] * v2[2] + u3[i] * v3[2]);
    }

#pragma unroll
    for (int i = 0; i < 3; i++)
#pragma unroll
        for (int j = 0; j < 3; j++)
            out_rot[(size_t)f * 9 + i * 3 + j] = R[i][j];

    float t0 = o12[9];
    float t1 = o12[10];
    float t2 = o12[11];

#pragma unroll
    for (int c = 0; c < 3; c++) {
        int vi = faces[f * 3 + c];
        float vx = verts[(size_t)vi * 3 + 0];
        float vy = verts[(size_t)vi * 3 + 1];
        float vz = verts[(size_t)vi * 3 + 2];
        float tvx = vx * R[0][0] + vy * R[1][0] + vz * R[2][0] + t0;
        float tvy = vx * R[0][1] + vy * R[1][1] + vz * R[2][1] + t1;
        float tvz = vx * R[0][2] + vy * R[1][2] + vz * R[2][2] + t2;
        out_trans[(size_t)f * 9 + c * 3 + 0] = tvx;
        out_trans[(size_t)f * 9 + c * 3 + 1] = tvy;
        out_trans[(size_t)f * 9 + c * 3 + 2] = tvz;
        atomicAdd(&g_sum[vi * 3 + 0], tvx);
        atomicAdd(&g_sum[vi * 3 + 1], tvy);
        atomicAdd(&g_sum[vi * 3 + 2], tvz);
        atomicAdd(&g_cnt[vi], 1.0f);
    }
}

// ===================== finalize segment mean =====================
__global__ void finalize_kernel(float* __restrict__ out_vfeat) {
    int v = blockIdx.x * blockDim.x + threadIdx.x;
    if (v >= N_VERTS) return;
    float c = fmaxf(g_cnt[v], 1.0f);
    float inv = 1.0f / c;
    out_vfeat[v * 3 + 0] = g_sum[v * 3 + 0] * inv;
    out_vfeat[v * 3 + 1] = g_sum[v * 3 + 1] * inv;
    out_vfeat[v * 3 + 2] = g_sum[v * 3 + 2] * inv;
}

// ===================== launch =====================
extern "C" void kernel_launch(void* const* d_in, const int* in_sizes, int n_in,
                              void* d_out, int out_size) {
    const float* verts    = (const float*)d_in[0];
    const float* features = (const float*)d_in[1];
    const int*   faces    = (const int*)d_in[2];
    const float* W1 = (const float*)d_in[3];
    const float* b1 = (const float*)d_in[4];
    const float* W2 = (const float*)d_in[5];
    const float* b2 = (const float*)d_in[6];
    const float* W3 = (const float*)d_in[7];
    const float* b3 = (const float*)d_in[8];
    const float* W4 = (const float*)d_in[9];
    const float* b4 = (const float*)d_in[10];

    float* out = (float*)d_out;
    float* out_vfeat = out;
    float* out_trans = out + (size_t)N_VERTS * 3;
    float* out_rot   = out_trans + (size_t)N_FACES * 9;

    __half *p_f_hi, *p_f_lo, *p_x_hi, *p_x_lo, *p_y_hi, *p_y_lo;
    __half *p_w1t, *p_w2t, *p_w3t;
    float *p_G, *p_p12;
    cudaGetSymbolAddress((void**)&p_f_hi, g_f_hi);
    cudaGetSymbolAddress((void**)&p_f_lo, g_f_lo);
    cudaGetSymbolAddress((void**)&p_G, g_G);
    cudaGetSymbolAddress((void**)&p_x_hi, g_x_hi);
    cudaGetSymbolAddress((void**)&p_x_lo, g_x_lo);
    cudaGetSymbolAddress((void**)&p_y_hi, g_y_hi);
    cudaGetSymbolAddress((void**)&p_y_lo, g_y_lo);
    cudaGetSymbolAddress((void**)&p_w1t, g_w1t);
    cudaGetSymbolAddress((void**)&p_w2t, g_w2t);
    cudaGetSymbolAddress((void**)&p_w3t, g_w3t);
    cudaGetSymbolAddress((void**)&p_p12, g_p12);

    cudaFuncSetAttribute(gemm_hmma<512, 0>,
                         cudaFuncAttributeMaxDynamicSharedMemorySize, SM_TOTAL_G);
    cudaFuncSetAttribute(gemm_hmma<512, 2>,
                         cudaFuncAttributeMaxDynamicSharedMemorySize, SM_TOTAL_G);
    cudaFuncSetAttribute(gemm_hmma<256, 3>,
                         cudaFuncAttributeMaxDynamicSharedMemorySize, SM_TOTAL_G);

    // 1. prep: zero accumulators + convert weights + split features (1 launch)
    prep_kernel<<<(PREP_FEAT + 255) / 256, 256>>>(W1, W2, W3, features);

    // 2. G = features @ W1  (M = N_VERTS, raw f32 out)
    {
        dim3 blk(256);
        dim3 gG(4, (N_VERTS + 127) / 128);
        gemm_hmma<512, 2><<<gG, blk, SM_TOTAL_G>>>(p_f_hi, p_f_lo, p_w1t,
                                                   nullptr, p_G, nullptr, N_VERTS,
                                                   nullptr, nullptr);
    }

    // 3. h1 = relu(mean(G rows) + b1) -> fp16 split (per-face)
    gather_relu_split_kernel<<<N_FACES, 128>>>(p_G, faces, b1, p_x_hi, p_x_lo);

    // 4. layer 2; layer 3 fused with W4 head -> partial out12
    {
        dim3 blk(256);
        dim3 g12(4, (N_FACES + 127) / 128);
        gemm_hmma<512, 0><<<g12, blk, SM_TOTAL_G>>>(p_x_hi, p_x_lo, p_w2t,
                                                    b2, p_y_hi, p_y_lo, N_FACES,
                                                    nullptr, nullptr);
        dim3 g3(2, (N_FACES + 127) / 128);
        gemm_hmma<256, 3><<<g3, blk, SM_TOTAL_G>>>(p_y_hi, p_y_lo, p_w3t,
                                                   b3, nullptr, nullptr, N_FACES,
                                                   W4, p_p12);
    }

    // 5. procrustes (analytic eigensolver) + transform + scatter
    procrustes_kernel<<<(N_FACES + 255) / 256, 256>>>(p_p12, b4, verts, faces,
                                                      out_trans, out_rot);

    // 6. segment mean
    finalize_kernel<<<(N_VERTS + 255) / 256, 256>>>(out_vfeat);
}